// round 2
// baseline (speedup 1.0000x reference)
#include <cuda_runtime.h>
#include <math.h>

// ---------------------------------------------------------------------------
// Problem constants
// ---------------------------------------------------------------------------
#define BB      2
#define NVIEW   6
#define DIMC    128
#define HWQ     1024          // 32*32
#define HWK     1680          // 28*60
#define HEADS   4
#define DH      32
#define INNER   128
#define NKTOT   (NVIEW*HWK)   // 10080
#define ROWS_Q  (BB*NVIEW*HWQ)   // 12288
#define ROWS_K  (BB*NVIEW*HWK)   // 20160
#define ROWS_Z  (BB*HWQ)         // 2048
#define ATTN_SCALE 0.17677669529663687f  // 1/sqrt(32)

// ---------------------------------------------------------------------------
// Scratch (static device memory — no allocations anywhere)
// ---------------------------------------------------------------------------
__device__ float d_qx [ROWS_Q * DIMC];
__device__ float d_kx [ROWS_K * DIMC];
__device__ float d_vx [ROWS_K * DIMC];
__device__ float d_qp [ROWS_Q * DIMC];
__device__ float d_kp [ROWS_K * DIMC];
__device__ float d_vp [ROWS_K * DIMC];
__device__ float d_aout[ROWS_Z * DIMC];
__device__ float d_z1 [ROWS_Z * DIMC];
__device__ float d_zn [ROWS_Z * DIMC];
__device__ float d_hh [ROWS_Z * 256];
__device__ float d_m2 [ROWS_Z * DIMC];

// ---------------------------------------------------------------------------
// Kernel 1: LayerNorm over channel dim with CHW -> row-major gather.
// One block (128 threads) per row. x layout: [slab][128][HW], row = slab*HW+p.
// ---------------------------------------------------------------------------
__global__ void ln_rows_kernel(const float* __restrict__ x,
                               const float* __restrict__ g,
                               const float* __restrict__ bt,
                               float* __restrict__ y, int HW) {
    int row  = blockIdx.x;
    int slab = row / HW;
    int p    = row - slab * HW;
    int d    = threadIdx.x;                       // 0..127
    float v  = x[(slab * DIMC + d) * HW + p];

    float s = v, ss = v * v;
    #pragma unroll
    for (int o = 16; o; o >>= 1) {
        s  += __shfl_xor_sync(0xffffffffu, s,  o);
        ss += __shfl_xor_sync(0xffffffffu, ss, o);
    }
    __shared__ float sh[8];
    int w = d >> 5, l = d & 31;
    if (l == 0) { sh[w] = s; sh[4 + w] = ss; }
    __syncthreads();
    s  = sh[0] + sh[1] + sh[2] + sh[3];
    ss = sh[4] + sh[5] + sh[6] + sh[7];
    float mean = s * (1.f / 128.f);
    float var  = ss * (1.f / 128.f) - mean * mean;
    float rstd = rsqrtf(var + 1e-5f);
    y[row * DIMC + d] = (v - mean) * rstd * g[d] + bt[d];
}

// ---------------------------------------------------------------------------
// Kernel 2: C[M][N] = act(A[M][K] @ W[N][K]^T + bias[N])
// BM=BN=64, BK=16, 256 threads, 4x4 register tile.
// ---------------------------------------------------------------------------
template<bool GELU>
__global__ __launch_bounds__(256)
void gemm_bias_kernel(const float* __restrict__ A, const float* __restrict__ W,
                      const float* __restrict__ bias, float* __restrict__ C,
                      int M, int N, int K) {
    __shared__ __align__(16) float As[64 * 17];   // [r][k], pad 17
    __shared__ __align__(16) float Bs[16 * 68];   // [k][n], pad 68

    const int tid = threadIdx.x;
    const int tx  = tid & 15;       // col group
    const int ty  = tid >> 4;       // row group
    const int m0  = blockIdx.y * 64;
    const int n0  = blockIdx.x * 64;

    float acc[4][4] = {};

    for (int kt = 0; kt < K; kt += 16) {
        #pragma unroll
        for (int e = tid; e < 64 * 16; e += 256) {
            int r = e >> 4, k = e & 15;
            As[r * 17 + k] = A[(m0 + r) * K + kt + k];
        }
        #pragma unroll
        for (int e = tid; e < 16 * 64; e += 256) {
            int k = e & 15, n = e >> 4;
            Bs[k * 68 + n] = W[(n0 + n) * K + kt + k];
        }
        __syncthreads();
        #pragma unroll
        for (int kk = 0; kk < 16; ++kk) {
            float a0 = As[(ty * 4 + 0) * 17 + kk];
            float a1 = As[(ty * 4 + 1) * 17 + kk];
            float a2 = As[(ty * 4 + 2) * 17 + kk];
            float a3 = As[(ty * 4 + 3) * 17 + kk];
            float4 bv = *reinterpret_cast<const float4*>(&Bs[kk * 68 + tx * 4]);
            acc[0][0] += a0 * bv.x; acc[0][1] += a0 * bv.y; acc[0][2] += a0 * bv.z; acc[0][3] += a0 * bv.w;
            acc[1][0] += a1 * bv.x; acc[1][1] += a1 * bv.y; acc[1][2] += a1 * bv.z; acc[1][3] += a1 * bv.w;
            acc[2][0] += a2 * bv.x; acc[2][1] += a2 * bv.y; acc[2][2] += a2 * bv.z; acc[2][3] += a2 * bv.w;
            acc[3][0] += a3 * bv.x; acc[3][1] += a3 * bv.y; acc[3][2] += a3 * bv.z; acc[3][3] += a3 * bv.w;
        }
        __syncthreads();
    }

    #pragma unroll
    for (int i = 0; i < 4; ++i) {
        int row = m0 + ty * 4 + i;
        #pragma unroll
        for (int j = 0; j < 4; ++j) {
            int col = n0 + tx * 4 + j;
            float v = acc[i][j] + bias[col];
            if (GELU) v = 0.5f * v * (1.f + erff(v * 0.70710678118654752f));
            C[row * N + col] = v;
        }
    }
}

// ---------------------------------------------------------------------------
// Kernel 3: flash-style attention with joint softmax over n*K = 10080 keys.
// grid (Q/16, HEADS, B), 256 threads. Each warp owns 2 queries end-to-end.
// Chunk = 32 keys (315 chunks exactly).
// qp layout [(b*6+nn)*HWQ + q][128], head slice m*32.  kp/vp with HWK.
// ---------------------------------------------------------------------------
__global__ __launch_bounds__(256)
void attn_kernel(const float* __restrict__ qp, const float* __restrict__ kp,
                 const float* __restrict__ vp, float* __restrict__ aout) {
    const int qt = blockIdx.x, m = blockIdx.y, b = blockIdx.z;
    const int q0 = qt * 16;

    __shared__ float qs[16 * 6 * 32];   // [qq][nn][d]
    __shared__ float Ks[32 * 33];       // [j][d], pad 33
    __shared__ float Vs[32 * 33];

    const int tid = threadIdx.x;

    // Stage the 16 queries x 6 views.
    for (int e = tid; e < 16 * 6 * 32; e += 256) {
        int d  = e & 31;
        int nn = (e >> 5) % 6;
        int qq = e / 192;
        qs[e] = qp[((b * 6 + nn) * HWQ + q0 + qq) * DIMC + m * 32 + d];
    }

    const int w    = tid >> 5;
    const int lane = tid & 31;
    const int qa   = 2 * w, qb = qa + 1;

    float mA = -INFINITY, mB = -INFINITY;
    float lA = 0.f, lB = 0.f;
    float accA = 0.f, accB = 0.f;

    for (int c = 0; c < 315; ++c) {
        __syncthreads();
        // Stage 32 keys and 32 values (each 32-dim) for this head.
        for (int e = tid; e < 2048; e += 256) {
            int d   = e & 31;
            int j   = (e >> 5) & 31;
            int arr = e >> 10;               // 0 = K, 1 = V
            int kg  = c * 32 + j;
            int nn  = kg / HWK;
            int kk  = kg - nn * HWK;
            const float* src = arr ? vp : kp;
            float v = src[((b * 6 + nn) * HWK + kk) * DIMC + m * 32 + d];
            (arr ? Vs : Ks)[j * 33 + d] = v;
        }
        __syncthreads();

        // Logits: lane handles key j = lane for both of this warp's queries.
        int kg = c * 32 + lane;
        int nn = kg / HWK;
        const float* qA = &qs[(qa * 6 + nn) * 32];
        const float* qB = &qs[(qb * 6 + nn) * 32];
        float sA = 0.f, sB = 0.f;
        #pragma unroll
        for (int d = 0; d < 32; ++d) {
            float kv = Ks[lane * 33 + d];
            sA += kv * qA[d];
            sB += kv * qB[d];
        }
        sA *= ATTN_SCALE; sB *= ATTN_SCALE;

        // Online softmax update (per warp, per query).
        float cA = sA, cB = sB;
        #pragma unroll
        for (int o = 16; o; o >>= 1) {
            cA = fmaxf(cA, __shfl_xor_sync(0xffffffffu, cA, o));
            cB = fmaxf(cB, __shfl_xor_sync(0xffffffffu, cB, o));
        }
        float mnA = fmaxf(mA, cA), mnB = fmaxf(mB, cB);
        float eA = __expf(sA - mnA), eB = __expf(sB - mnB);
        float suA = eA, suB = eB;
        #pragma unroll
        for (int o = 16; o; o >>= 1) {
            suA += __shfl_xor_sync(0xffffffffu, suA, o);
            suB += __shfl_xor_sync(0xffffffffu, suB, o);
        }
        float alA = __expf(mA - mnA), alB = __expf(mB - mnB);
        lA = lA * alA + suA;  lB = lB * alB + suB;
        mA = mnA;             mB = mnB;
        accA *= alA;          accB *= alB;

        // AV: lane = output dim d; broadcast e_j via shuffle.
        #pragma unroll
        for (int j = 0; j < 32; ++j) {
            float vj = Vs[j * 33 + lane];
            accA += __shfl_sync(0xffffffffu, eA, j) * vj;
            accB += __shfl_sync(0xffffffffu, eB, j) * vj;
        }
    }

    // Merge heads: aout[b][q][m*32+d]
    aout[(b * HWQ + q0 + qa) * INNER + m * 32 + lane] = accA / lA;
    aout[(b * HWQ + q0 + qb) * INNER + m * 32 + lane] = accB / lB;
}

// ---------------------------------------------------------------------------
// Kernel 4: z = LN1(proj_out + skip(CHW)).  One block per row (b*HWQ+p).
// ---------------------------------------------------------------------------
__global__ void skip_ln_kernel(const float* __restrict__ z1,
                               const float* __restrict__ skip,
                               const float* __restrict__ g,
                               const float* __restrict__ bt,
                               float* __restrict__ zn) {
    int row = blockIdx.x;
    int b = row >> 10, p = row & 1023;
    int d = threadIdx.x;
    float v = z1[row * DIMC + d] + skip[(b * DIMC + d) * HWQ + p];

    float s = v, ss = v * v;
    #pragma unroll
    for (int o = 16; o; o >>= 1) {
        s  += __shfl_xor_sync(0xffffffffu, s,  o);
        ss += __shfl_xor_sync(0xffffffffu, ss, o);
    }
    __shared__ float sh[8];
    int w = d >> 5, l = d & 31;
    if (l == 0) { sh[w] = s; sh[4 + w] = ss; }
    __syncthreads();
    s  = sh[0] + sh[1] + sh[2] + sh[3];
    ss = sh[4] + sh[5] + sh[6] + sh[7];
    float mean = s * (1.f / 128.f);
    float rstd = rsqrtf(ss * (1.f / 128.f) - mean * mean + 1e-5f);
    zn[row * DIMC + d] = (v - mean) * rstd * g[d] + bt[d];
}

// ---------------------------------------------------------------------------
// Kernel 5: out(CHW) = LN2(zn + mlp_out).  One block per row.
// ---------------------------------------------------------------------------
__global__ void final_ln_kernel(const float* __restrict__ zn,
                                const float* __restrict__ m2,
                                const float* __restrict__ g,
                                const float* __restrict__ bt,
                                float* __restrict__ out) {
    int row = blockIdx.x;
    int b = row >> 10, p = row & 1023;
    int d = threadIdx.x;
    float v = zn[row * DIMC + d] + m2[row * DIMC + d];

    float s = v, ss = v * v;
    #pragma unroll
    for (int o = 16; o; o >>= 1) {
        s  += __shfl_xor_sync(0xffffffffu, s,  o);
        ss += __shfl_xor_sync(0xffffffffu, ss, o);
    }
    __shared__ float sh[8];
    int w = d >> 5, l = d & 31;
    if (l == 0) { sh[w] = s; sh[4 + w] = ss; }
    __syncthreads();
    s  = sh[0] + sh[1] + sh[2] + sh[3];
    ss = sh[4] + sh[5] + sh[6] + sh[7];
    float mean = s * (1.f / 128.f);
    float rstd = rsqrtf(ss * (1.f / 128.f) - mean * mean + 1e-5f);
    out[(b * DIMC + d) * HWQ + p] = (v - mean) * rstd * g[d] + bt[d];
}

// ---------------------------------------------------------------------------
// Launcher
// ---------------------------------------------------------------------------
extern "C" void kernel_launch(void* const* d_in, const int* in_sizes, int n_in,
                              void* d_out, int out_size) {
    const float* q     = (const float*)d_in[0];
    const float* k     = (const float*)d_in[1];
    const float* v     = (const float*)d_in[2];
    const float* skip  = (const float*)d_in[3];
    const float* lnq_g = (const float*)d_in[4];
    const float* lnq_b = (const float*)d_in[5];
    const float* Wq    = (const float*)d_in[6];
    const float* bq    = (const float*)d_in[7];
    const float* lnk_g = (const float*)d_in[8];
    const float* lnk_b = (const float*)d_in[9];
    const float* Wk    = (const float*)d_in[10];
    const float* bk    = (const float*)d_in[11];
    const float* lnv_g = (const float*)d_in[12];
    const float* lnv_b = (const float*)d_in[13];
    const float* Wv    = (const float*)d_in[14];
    const float* bv    = (const float*)d_in[15];
    const float* Wp    = (const float*)d_in[16];
    const float* bp    = (const float*)d_in[17];
    const float* ln1_g = (const float*)d_in[18];
    const float* ln1_b = (const float*)d_in[19];
    const float* W1    = (const float*)d_in[20];
    const float* b1    = (const float*)d_in[21];
    const float* W2    = (const float*)d_in[22];
    const float* b2    = (const float*)d_in[23];
    const float* ln2_g = (const float*)d_in[24];
    const float* ln2_b = (const float*)d_in[25];
    float* out = (float*)d_out;

    float *qx, *kx, *vx, *qp, *kp, *vp, *aout, *z1, *zn, *hh, *m2;
    cudaGetSymbolAddress((void**)&qx,   d_qx);
    cudaGetSymbolAddress((void**)&kx,   d_kx);
    cudaGetSymbolAddress((void**)&vx,   d_vx);
    cudaGetSymbolAddress((void**)&qp,   d_qp);
    cudaGetSymbolAddress((void**)&kp,   d_kp);
    cudaGetSymbolAddress((void**)&vp,   d_vp);
    cudaGetSymbolAddress((void**)&aout, d_aout);
    cudaGetSymbolAddress((void**)&z1,   d_z1);
    cudaGetSymbolAddress((void**)&zn,   d_zn);
    cudaGetSymbolAddress((void**)&hh,   d_hh);
    cudaGetSymbolAddress((void**)&m2,   d_m2);

    // 1. LayerNorms (CHW gather -> row-major xhat)
    ln_rows_kernel<<<ROWS_Q, 128>>>(q, lnq_g, lnq_b, qx, HWQ);
    ln_rows_kernel<<<ROWS_K, 128>>>(k, lnk_g, lnk_b, kx, HWK);
    ln_rows_kernel<<<ROWS_K, 128>>>(v, lnv_g, lnv_b, vx, HWK);

    // 2. Projections
    gemm_bias_kernel<false><<<dim3(2, ROWS_Q / 64), 256>>>(qx, Wq, bq, qp, ROWS_Q, 128, 128);
    gemm_bias_kernel<false><<<dim3(2, ROWS_K / 64), 256>>>(kx, Wk, bk, kp, ROWS_K, 128, 128);
    gemm_bias_kernel<false><<<dim3(2, ROWS_K / 64), 256>>>(vx, Wv, bv, vp, ROWS_K, 128, 128);

    // 3. Attention (joint softmax over all views)
    attn_kernel<<<dim3(HWQ / 16, HEADS, BB), 256>>>(qp, kp, vp, aout);

    // 4. Output projection + skip + LN1
    gemm_bias_kernel<false><<<dim3(2, ROWS_Z / 64), 256>>>(aout, Wp, bp, z1, ROWS_Z, 128, 128);
    skip_ln_kernel<<<ROWS_Z, 128>>>(z1, skip, ln1_g, ln1_b, zn);

    // 5. MLP (GELU exact) + residual + LN2 + NCHW output
    gemm_bias_kernel<true ><<<dim3(4, ROWS_Z / 64), 256>>>(zn, W1, b1, hh, ROWS_Z, 256, 128);
    gemm_bias_kernel<false><<<dim3(2, ROWS_Z / 64), 256>>>(hh, W2, b2, m2, ROWS_Z, 128, 256);
    final_ln_kernel<<<ROWS_Z, 128>>>(zn, m2, ln2_g, ln2_b, out);
}

// round 5
// speedup vs baseline: 1.4625x; 1.4625x over previous
#include <cuda_runtime.h>
#include <math.h>

// ---------------------------------------------------------------------------
// Problem constants
// ---------------------------------------------------------------------------
#define BB      2
#define NVIEW   6
#define DIMC    128
#define HWQ     1024          // 32*32
#define HWK     1680          // 28*60
#define HEADS   4
#define DH      32
#define INNER   128
#define NKTOT   (NVIEW*HWK)   // 10080
#define ROWS_Q  (BB*NVIEW*HWQ)   // 12288
#define ROWS_K  (BB*NVIEW*HWK)   // 20160
#define ROWS_Z  (BB*HWQ)         // 2048
#define ATTN_SCALE 0.17677669529663687f  // 1/sqrt(32)

// Attention tiling
#define TQ   16                // queries per block
#define KC   48                // keys per chunk (1680 = 35*48)
#define KSTR 36                // padded row stride for Ks/Vs (floats, 16B aligned)
#define PSTR 52                // padded row stride for Ps (floats, 16B aligned)

// ---------------------------------------------------------------------------
// Scratch (static device memory — no allocations anywhere)
// ---------------------------------------------------------------------------
__device__ float d_qx [ROWS_Q * DIMC];
__device__ float d_kx [ROWS_K * DIMC];
__device__ float d_vx [ROWS_K * DIMC];
__device__ float d_qp [ROWS_Q * DIMC];
__device__ float d_kp [ROWS_K * DIMC];
__device__ float d_vp [ROWS_K * DIMC];
__device__ float d_aout[ROWS_Z * DIMC];
__device__ float d_z1 [ROWS_Z * DIMC];
__device__ float d_zn [ROWS_Z * DIMC];
__device__ float d_hh [ROWS_Z * 256];
__device__ float d_m2 [ROWS_Z * DIMC];

// ---------------------------------------------------------------------------
// Kernel 1: LayerNorm over channel dim with CHW -> row-major gather.
// ---------------------------------------------------------------------------
__global__ void ln_rows_kernel(const float* __restrict__ x,
                               const float* __restrict__ g,
                               const float* __restrict__ bt,
                               float* __restrict__ y, int HW) {
    int row  = blockIdx.x;
    int slab = row / HW;
    int p    = row - slab * HW;
    int d    = threadIdx.x;                       // 0..127
    float v  = x[(slab * DIMC + d) * HW + p];

    float s = v, ss = v * v;
    #pragma unroll
    for (int o = 16; o; o >>= 1) {
        s  += __shfl_xor_sync(0xffffffffu, s,  o);
        ss += __shfl_xor_sync(0xffffffffu, ss, o);
    }
    __shared__ float sh[8];
    int w = d >> 5, l = d & 31;
    if (l == 0) { sh[w] = s; sh[4 + w] = ss; }
    __syncthreads();
    s  = sh[0] + sh[1] + sh[2] + sh[3];
    ss = sh[4] + sh[5] + sh[6] + sh[7];
    float mean = s * (1.f / 128.f);
    float var  = ss * (1.f / 128.f) - mean * mean;
    float rstd = rsqrtf(var + 1e-5f);
    y[row * DIMC + d] = (v - mean) * rstd * g[d] + bt[d];
}

// ---------------------------------------------------------------------------
// Kernel 2: C[M][N] = act(A[M][K] @ W[N][K]^T + bias[N])
// ---------------------------------------------------------------------------
template<bool GELU>
__global__ __launch_bounds__(256)
void gemm_bias_kernel(const float* __restrict__ A, const float* __restrict__ W,
                      const float* __restrict__ bias, float* __restrict__ C,
                      int M, int N, int K) {
    __shared__ __align__(16) float As[64 * 17];
    __shared__ __align__(16) float Bs[16 * 68];

    const int tid = threadIdx.x;
    const int tx  = tid & 15;
    const int ty  = tid >> 4;
    const int m0  = blockIdx.y * 64;
    const int n0  = blockIdx.x * 64;

    float acc[4][4] = {};

    for (int kt = 0; kt < K; kt += 16) {
        #pragma unroll
        for (int e = tid; e < 64 * 16; e += 256) {
            int r = e >> 4, k = e & 15;
            As[r * 17 + k] = A[(m0 + r) * K + kt + k];
        }
        #pragma unroll
        for (int e = tid; e < 16 * 64; e += 256) {
            int k = e & 15, n = e >> 4;
            Bs[k * 68 + n] = W[(n0 + n) * K + kt + k];
        }
        __syncthreads();
        #pragma unroll
        for (int kk = 0; kk < 16; ++kk) {
            float a0 = As[(ty * 4 + 0) * 17 + kk];
            float a1 = As[(ty * 4 + 1) * 17 + kk];
            float a2 = As[(ty * 4 + 2) * 17 + kk];
            float a3 = As[(ty * 4 + 3) * 17 + kk];
            float4 bv = *reinterpret_cast<const float4*>(&Bs[kk * 68 + tx * 4]);
            acc[0][0] += a0 * bv.x; acc[0][1] += a0 * bv.y; acc[0][2] += a0 * bv.z; acc[0][3] += a0 * bv.w;
            acc[1][0] += a1 * bv.x; acc[1][1] += a1 * bv.y; acc[1][2] += a1 * bv.z; acc[1][3] += a1 * bv.w;
            acc[2][0] += a2 * bv.x; acc[2][1] += a2 * bv.y; acc[2][2] += a2 * bv.z; acc[2][3] += a2 * bv.w;
            acc[3][0] += a3 * bv.x; acc[3][1] += a3 * bv.y; acc[3][2] += a3 * bv.z; acc[3][3] += a3 * bv.w;
        }
        __syncthreads();
    }

    #pragma unroll
    for (int i = 0; i < 4; ++i) {
        int row = m0 + ty * 4 + i;
        #pragma unroll
        for (int j = 0; j < 4; ++j) {
            int col = n0 + tx * 4 + j;
            float v = acc[i][j] + bias[col];
            if (GELU) v = 0.5f * v * (1.f + erff(v * 0.70710678118654752f));
            C[row * N + col] = v;
        }
    }
}

// ---------------------------------------------------------------------------
// Kernel 3: flash attention, two-GEMM register-tiled, joint softmax over
// 6 views * 1680 keys. Block = 16 queries x (head, batch). 128 threads.
// Per view: 35 chunks of 48 keys (exact).
// ---------------------------------------------------------------------------
__global__ __launch_bounds__(128)
void attn_kernel(const float* __restrict__ qp, const float* __restrict__ kp,
                 const float* __restrict__ vp, float* __restrict__ aout) {
    const int qt = blockIdx.x, m = blockIdx.y, b = blockIdx.z;
    const int q0 = qt * TQ;
    const int tid = threadIdx.x;

    __shared__ __align__(16) float qs[TQ * NVIEW * DH];   // [qq][nn][d]
    __shared__ __align__(16) float Ks[KC * KSTR];
    __shared__ __align__(16) float Vs[KC * KSTR];
    __shared__ __align__(16) float Ps[TQ * PSTR];         // S then P in place

    // ---- stage queries: 16 q x 6 views x 32 dims = 768 float4 loads ----
    {
        const float* qbase = qp + (size_t)b * 6 * HWQ * DIMC + (size_t)m * DH;
        #pragma unroll
        for (int r = 0; r < 6; ++r) {
            int e  = tid + r * 128;              // 0..767
            int d4 = e & 7;
            int nn = (e >> 3) % 6;
            int qq = e / 48;
            float4 v = *reinterpret_cast<const float4*>(
                &qbase[((size_t)nn * HWQ + q0 + qq) * DIMC + d4 * 4]);
            *reinterpret_cast<float4*>(&qs[(qq * 6 + nn) * DH + d4 * 4]) = v;
        }
    }

    // S-phase mapping: kg = tid&15 (3 keys each), qg = tid>>4 (2 queries each)
    const int kg = tid & 15;
    const int qg = tid >> 4;
    // softmax/AV mapping: q = tid>>3, t = tid&7 (4 dims each)
    const int sq = tid >> 3;
    const int st = tid & 7;

    float o0 = 0.f, o1 = 0.f, o2 = 0.f, o3 = 0.f;
    float mrun = -INFINITY, lrun = 0.f;

    for (int nn = 0; nn < NVIEW; ++nn) {
        const float* kvbase = kp + ((size_t)(b * 6 + nn) * HWK) * DIMC + m * DH;
        const float* vvbase = vp + ((size_t)(b * 6 + nn) * HWK) * DIMC + m * DH;
        const float* qA = &qs[((qg * 2 + 0) * 6 + nn) * DH];
        const float* qB = &qs[((qg * 2 + 1) * 6 + nn) * DH];

        for (int c = 0; c < HWK / KC; ++c) {
            __syncthreads();   // previous chunk fully consumed

            // ---- stage K,V chunk: 48 rows x 32 dims, float4 coalesced ----
            {
                const float* kc = kvbase + (size_t)(c * KC) * DIMC;
                const float* vc = vvbase + (size_t)(c * KC) * DIMC;
                #pragma unroll
                for (int r = 0; r < 3; ++r) {
                    int e   = tid + r * 128;     // 0..383
                    int d4  = e & 7;
                    int row = e >> 3;            // 0..47
                    *reinterpret_cast<float4*>(&Ks[row * KSTR + d4 * 4]) =
                        *reinterpret_cast<const float4*>(&kc[(size_t)row * DIMC + d4 * 4]);
                    *reinterpret_cast<float4*>(&Vs[row * KSTR + d4 * 4]) =
                        *reinterpret_cast<const float4*>(&vc[(size_t)row * DIMC + d4 * 4]);
                }
            }
            __syncthreads();

            // ---- S = Q K^T (2q x 3k per thread) ----
            float acc[2][3] = {};
            #pragma unroll
            for (int d4 = 0; d4 < 8; ++d4) {
                float4 qa = *reinterpret_cast<const float4*>(&qA[d4 * 4]);
                float4 qb = *reinterpret_cast<const float4*>(&qB[d4 * 4]);
                #pragma unroll
                for (int j = 0; j < 3; ++j) {
                    float4 kv = *reinterpret_cast<const float4*>(&Ks[(kg * 3 + j) * KSTR + d4 * 4]);
                    acc[0][j] += qa.x * kv.x + qa.y * kv.y + qa.z * kv.z + qa.w * kv.w;
                    acc[1][j] += qb.x * kv.x + qb.y * kv.y + qb.z * kv.z + qb.w * kv.w;
                }
            }
            #pragma unroll
            for (int i = 0; i < 2; ++i)
                #pragma unroll
                for (int j = 0; j < 3; ++j)
                    Ps[(qg * 2 + i) * PSTR + kg * 3 + j] = acc[i][j] * ATTN_SCALE;
            __syncthreads();

            // ---- online softmax (8-lane groups, one query each) ----
            float sv[6];
            float cmax = -INFINITY;
            #pragma unroll
            for (int i = 0; i < 6; ++i) {
                sv[i] = Ps[sq * PSTR + st + 8 * i];
                cmax = fmaxf(cmax, sv[i]);
            }
            #pragma unroll
            for (int o = 4; o; o >>= 1)
                cmax = fmaxf(cmax, __shfl_xor_sync(0xffffffffu, cmax, o));
            float mnew = fmaxf(mrun, cmax);
            float lsum = 0.f;
            #pragma unroll
            for (int i = 0; i < 6; ++i) {
                float e = __expf(sv[i] - mnew);
                Ps[sq * PSTR + st + 8 * i] = e;
                lsum += e;
            }
            #pragma unroll
            for (int o = 4; o; o >>= 1)
                lsum += __shfl_xor_sync(0xffffffffu, lsum, o);
            float alpha = __expf(mrun - mnew);
            lrun = lrun * alpha + lsum;
            mrun = mnew;
            o0 *= alpha; o1 *= alpha; o2 *= alpha; o3 *= alpha;
            __syncwarp();

            // ---- O += P V (1q x 4d per thread) ----
            #pragma unroll
            for (int j4 = 0; j4 < KC / 4; ++j4) {
                float4 pv = *reinterpret_cast<const float4*>(&Ps[sq * PSTR + j4 * 4]);
                float4 v0 = *reinterpret_cast<const float4*>(&Vs[(j4 * 4 + 0) * KSTR + st * 4]);
                float4 v1 = *reinterpret_cast<const float4*>(&Vs[(j4 * 4 + 1) * KSTR + st * 4]);
                float4 v2 = *reinterpret_cast<const float4*>(&Vs[(j4 * 4 + 2) * KSTR + st * 4]);
                float4 v3 = *reinterpret_cast<const float4*>(&Vs[(j4 * 4 + 3) * KSTR + st * 4]);
                o0 += pv.x * v0.x + pv.y * v1.x + pv.z * v2.x + pv.w * v3.x;
                o1 += pv.x * v0.y + pv.y * v1.y + pv.z * v2.y + pv.w * v3.y;
                o2 += pv.x * v0.z + pv.y * v1.z + pv.z * v2.z + pv.w * v3.z;
                o3 += pv.x * v0.w + pv.y * v1.w + pv.z * v2.w + pv.w * v3.w;
            }
        }
    }

    float inv = 1.f / lrun;
    float4 outv = make_float4(o0 * inv, o1 * inv, o2 * inv, o3 * inv);
    *reinterpret_cast<float4*>(
        &aout[((size_t)(b * HWQ + q0 + sq)) * INNER + m * DH + st * 4]) = outv;
}

// ---------------------------------------------------------------------------
// Kernel 4: z = LN1(proj_out + skip(CHW)).
// ---------------------------------------------------------------------------
__global__ void skip_ln_kernel(const float* __restrict__ z1,
                               const float* __restrict__ skip,
                               const float* __restrict__ g,
                               const float* __restrict__ bt,
                               float* __restrict__ zn) {
    int row = blockIdx.x;
    int b = row >> 10, p = row & 1023;
    int d = threadIdx.x;
    float v = z1[row * DIMC + d] + skip[(b * DIMC + d) * HWQ + p];

    float s = v, ss = v * v;
    #pragma unroll
    for (int o = 16; o; o >>= 1) {
        s  += __shfl_xor_sync(0xffffffffu, s,  o);
        ss += __shfl_xor_sync(0xffffffffu, ss, o);
    }
    __shared__ float sh[8];
    int w = d >> 5, l = d & 31;
    if (l == 0) { sh[w] = s; sh[4 + w] = ss; }
    __syncthreads();
    s  = sh[0] + sh[1] + sh[2] + sh[3];
    ss = sh[4] + sh[5] + sh[6] + sh[7];
    float mean = s * (1.f / 128.f);
    float rstd = rsqrtf(ss * (1.f / 128.f) - mean * mean + 1e-5f);
    zn[row * DIMC + d] = (v - mean) * rstd * g[d] + bt[d];
}

// ---------------------------------------------------------------------------
// Kernel 5: out(CHW) = LN2(zn + mlp_out).
// ---------------------------------------------------------------------------
__global__ void final_ln_kernel(const float* __restrict__ zn,
                                const float* __restrict__ m2,
                                const float* __restrict__ g,
                                const float* __restrict__ bt,
                                float* __restrict__ out) {
    int row = blockIdx.x;
    int b = row >> 10, p = row & 1023;
    int d = threadIdx.x;
    float v = zn[row * DIMC + d] + m2[row * DIMC + d];

    float s = v, ss = v * v;
    #pragma unroll
    for (int o = 16; o; o >>= 1) {
        s  += __shfl_xor_sync(0xffffffffu, s,  o);
        ss += __shfl_xor_sync(0xffffffffu, ss, o);
    }
    __shared__ float sh[8];
    int w = d >> 5, l = d & 31;
    if (l == 0) { sh[w] = s; sh[4 + w] = ss; }
    __syncthreads();
    s  = sh[0] + sh[1] + sh[2] + sh[3];
    ss = sh[4] + sh[5] + sh[6] + sh[7];
    float mean = s * (1.f / 128.f);
    float rstd = rsqrtf(ss * (1.f / 128.f) - mean * mean + 1e-5f);
    out[(b * DIMC + d) * HWQ + p] = (v - mean) * rstd * g[d] + bt[d];
}

// ---------------------------------------------------------------------------
// Launcher
// ---------------------------------------------------------------------------
extern "C" void kernel_launch(void* const* d_in, const int* in_sizes, int n_in,
                              void* d_out, int out_size) {
    const float* q     = (const float*)d_in[0];
    const float* k     = (const float*)d_in[1];
    const float* v     = (const float*)d_in[2];
    const float* skip  = (const float*)d_in[3];
    const float* lnq_g = (const float*)d_in[4];
    const float* lnq_b = (const float*)d_in[5];
    const float* Wq    = (const float*)d_in[6];
    const float* bq    = (const float*)d_in[7];
    const float* lnk_g = (const float*)d_in[8];
    const float* lnk_b = (const float*)d_in[9];
    const float* Wk    = (const float*)d_in[10];
    const float* bk    = (const float*)d_in[11];
    const float* lnv_g = (const float*)d_in[12];
    const float* lnv_b = (const float*)d_in[13];
    const float* Wv    = (const float*)d_in[14];
    const float* bv    = (const float*)d_in[15];
    const float* Wp    = (const float*)d_in[16];
    const float* bp    = (const float*)d_in[17];
    const float* ln1_g = (const float*)d_in[18];
    const float* ln1_b = (const float*)d_in[19];
    const float* W1    = (const float*)d_in[20];
    const float* b1    = (const float*)d_in[21];
    const float* W2    = (const float*)d_in[22];
    const float* b2    = (const float*)d_in[23];
    const float* ln2_g = (const float*)d_in[24];
    const float* ln2_b = (const float*)d_in[25];
    float* out = (float*)d_out;

    float *qx, *kx, *vx, *qp, *kp, *vp, *aout, *z1, *zn, *hh, *m2;
    cudaGetSymbolAddress((void**)&qx,   d_qx);
    cudaGetSymbolAddress((void**)&kx,   d_kx);
    cudaGetSymbolAddress((void**)&vx,   d_vx);
    cudaGetSymbolAddress((void**)&qp,   d_qp);
    cudaGetSymbolAddress((void**)&kp,   d_kp);
    cudaGetSymbolAddress((void**)&vp,   d_vp);
    cudaGetSymbolAddress((void**)&aout, d_aout);
    cudaGetSymbolAddress((void**)&z1,   d_z1);
    cudaGetSymbolAddress((void**)&zn,   d_zn);
    cudaGetSymbolAddress((void**)&hh,   d_hh);
    cudaGetSymbolAddress((void**)&m2,   d_m2);

    // 1. LayerNorms (CHW gather -> row-major xhat)
    ln_rows_kernel<<<ROWS_Q, 128>>>(q, lnq_g, lnq_b, qx, HWQ);
    ln_rows_kernel<<<ROWS_K, 128>>>(k, lnk_g, lnk_b, kx, HWK);
    ln_rows_kernel<<<ROWS_K, 128>>>(v, lnv_g, lnv_b, vx, HWK);

    // 2. Projections
    gemm_bias_kernel<false><<<dim3(2, ROWS_Q / 64), 256>>>(qx, Wq, bq, qp, ROWS_Q, 128, 128);
    gemm_bias_kernel<false><<<dim3(2, ROWS_K / 64), 256>>>(kx, Wk, bk, kp, ROWS_K, 128, 128);
    gemm_bias_kernel<false><<<dim3(2, ROWS_K / 64), 256>>>(vx, Wv, bv, vp, ROWS_K, 128, 128);

    // 3. Attention (joint softmax over all views)
    attn_kernel<<<dim3(HWQ / TQ, HEADS, BB), 128>>>(qp, kp, vp, aout);

    // 4. Output projection + skip + LN1
    gemm_bias_kernel<false><<<dim3(2, ROWS_Z / 64), 256>>>(aout, Wp, bp, z1, ROWS_Z, 128, 128);
    skip_ln_kernel<<<ROWS_Z, 128>>>(z1, skip, ln1_g, ln1_b, zn);

    // 5. MLP (GELU exact) + residual + LN2 + NCHW output
    gemm_bias_kernel<true ><<<dim3(4, ROWS_Z / 64), 256>>>(zn, W1, b1, hh, ROWS_Z, 256, 128);
    gemm_bias_kernel<false><<<dim3(2, ROWS_Z / 64), 256>>>(hh, W2, b2, m2, ROWS_Z, 128, 256);
    final_ln_kernel<<<ROWS_Z, 128>>>(zn, m2, ln2_g, ln2_b, out);
}